// round 1
// baseline (speedup 1.0000x reference)
#include <cuda_runtime.h>

// Problem constants
#define NB   32          // batch
#define CIN  64
#define COUT 128
#define KK   4
#define HW   (64*64)     // 4096 spatial elems per (n,ci)
#define OHW  4489.0f     // (64+3)^2 output spatial size

// Scratch (no allocations allowed)
__device__ float g_Sx[NB * CIN];      // 2048
__device__ float g_Sw[CIN * COUT];    // 8192

__device__ __forceinline__ float warp_sum(float v) {
    v += __shfl_xor_sync(0xffffffffu, v, 16);
    v += __shfl_xor_sync(0xffffffffu, v, 8);
    v += __shfl_xor_sync(0xffffffffu, v, 4);
    v += __shfl_xor_sync(0xffffffffu, v, 2);
    v += __shfl_xor_sync(0xffffffffu, v, 1);
    return v;
}
__device__ __forceinline__ float warp_max(float v) {
    v = fmaxf(v, __shfl_xor_sync(0xffffffffu, v, 16));
    v = fmaxf(v, __shfl_xor_sync(0xffffffffu, v, 8));
    v = fmaxf(v, __shfl_xor_sync(0xffffffffu, v, 4));
    v = fmaxf(v, __shfl_xor_sync(0xffffffffu, v, 2));
    v = fmaxf(v, __shfl_xor_sync(0xffffffffu, v, 1));
    return v;
}

// Launch 1: blocks [0, 2048): Sx[n*CIN+ci] = sum over 4096 spatial floats.
//           blocks [2048, 2048+64): Sw[ci*COUT+co] = sum over 16 kernel taps.
__global__ void reduce_kernel(const float* __restrict__ x,
                              const float* __restrict__ w) {
    const int b = blockIdx.x;
    if (b < NB * CIN) {
        // ---- Sx: 256 threads, 4096 elems, float4 loads ----
        const float4* p = reinterpret_cast<const float4*>(x) + (size_t)b * (HW / 4);
        float s = 0.0f;
        #pragma unroll
        for (int i = 0; i < 4; i++) {
            float4 v = p[threadIdx.x + i * 256];
            s += (v.x + v.y) + (v.z + v.w);
        }
        s = warp_sum(s);
        __shared__ float sh[8];
        const int lane = threadIdx.x & 31;
        const int wid  = threadIdx.x >> 5;
        if (lane == 0) sh[wid] = s;
        __syncthreads();
        if (wid == 0) {
            float t = (lane < 8) ? sh[lane] : 0.0f;
            t += __shfl_xor_sync(0xffffffffu, t, 4);
            t += __shfl_xor_sync(0xffffffffu, t, 2);
            t += __shfl_xor_sync(0xffffffffu, t, 1);
            if (lane == 0) g_Sx[b] = t;
        }
    } else {
        // ---- Sw: one block per ci, thread co sums its 16 contiguous taps ----
        const int ci = b - NB * CIN;
        const int co = threadIdx.x;
        if (co < COUT) {
            const float4* p = reinterpret_cast<const float4*>(w)
                            + ((size_t)ci * COUT + co) * (KK * KK / 4);
            float4 a0 = p[0], a1 = p[1], a2 = p[2], a3 = p[3];
            float s = ((a0.x + a0.y) + (a0.z + a0.w))
                    + ((a1.x + a1.y) + (a1.z + a1.w))
                    + ((a2.x + a2.y) + (a2.z + a2.w))
                    + ((a3.x + a3.y) + (a3.z + a3.w));
            g_Sw[ci * COUT + co] = s;
        }
    }
}

// Launch 2: one block per n, 128 threads (one per co).
// pooled = dot(Sx[n,:], Sw[:,co]) / OHW + cb[co] + eb[co]; out = 10*LSE.
__global__ void finalize_kernel(const float* __restrict__ cb,
                                const float* __restrict__ eb,
                                float* __restrict__ out) {
    const int n  = blockIdx.x;
    const int co = threadIdx.x;
    const int lane = co & 31;
    const int wid  = co >> 5;

    __shared__ float sx[CIN];
    if (co < CIN) sx[co] = g_Sx[n * CIN + co];
    __syncthreads();

    float acc = 0.0f;
    #pragma unroll
    for (int ci = 0; ci < CIN; ci++) {
        acc = fmaf(sx[ci], g_Sw[ci * COUT + co], acc);
    }
    float pooled = acc * (1.0f / OHW) + cb[co] + eb[co];

    // block max over 128 (4 warps)
    __shared__ float red[4];
    float m = warp_max(pooled);
    if (lane == 0) red[wid] = m;
    __syncthreads();
    float m0 = fmaxf(fmaxf(red[0], red[1]), fmaxf(red[2], red[3]));

    // block sum of exp
    float e = __expf(pooled - m0);
    float s = warp_sum(e);
    __shared__ float red2[4];
    if (lane == 0) red2[wid] = s;
    __syncthreads();
    if (co == 0) {
        float tot = (red2[0] + red2[1]) + (red2[2] + red2[3]);
        out[n] = 10.0f * (m0 + logf(tot));
    }
}

extern "C" void kernel_launch(void* const* d_in, const int* in_sizes, int n_in,
                              void* d_out, int out_size) {
    const float* x  = (const float*)d_in[0];   // (32,64,64,64)
    const float* w  = (const float*)d_in[1];   // (64,128,4,4)
    const float* cb = (const float*)d_in[2];   // (128,)
    const float* eb = (const float*)d_in[3];   // (128,)
    float* out = (float*)d_out;                // (32,1)

    reduce_kernel<<<NB * CIN + CIN, 256>>>(x, w);
    finalize_kernel<<<NB, COUT>>>(cb, eb, out);
}